// round 1
// baseline (speedup 1.0000x reference)
#include <cuda_runtime.h>
#include <math.h>

// Problem constants
#define BB 4
#define NN 1024
#define DD 1024
#define HH 16
#define HDIM 64
#define MROWS (BB * NN)          // 4096

// Scratch (device globals; no allocations allowed)
__device__ float g_q[BB * HH * NN * HDIM];   // [B,H,N,HD]
__device__ float g_k[BB * HH * NN * HDIM];
__device__ float g_v[BB * HH * NN * HDIM];
__device__ float g_ctx[BB * NN * DD];        // [B,N,D] (H,HD interleaved = D)
__device__ float g_xm[MROWS * 2 * DD];       // concat([x, message]) rows of 2048
__device__ float g_h[MROWS * 2 * DD];        // FFN hidden, rows of 2048

// ---------------------------------------------------------------------------
// Generic tiled SGEMM:  C[M,Ncol] = A[M,K] @ W[Ncol,K]^T + bias
// mode 0: A=g_xm   -> g_h                      (FFN1)
// mode 1: A=Ain(x) -> scatter to g_q/g_k/g_v   (QKV)
// mode 2: A=g_ctx  -> g_xm[:,1024:2048]        (out-proj)
// mode 3: A=g_h    -> Cout = resid + result    (FFN2 + residual)
// ---------------------------------------------------------------------------
#define BM 128
#define BN 128
#define BK 16
#define AP 132   // smem pitch (floats), keeps float4 alignment, avoids store conflicts

__global__ __launch_bounds__(256) void gemm_kernel(
    const float* __restrict__ Ain, const float* __restrict__ W,
    const float* __restrict__ bias, float* __restrict__ Cout,
    const float* __restrict__ resid, int M, int Ncol, int K, int mode)
{
    __shared__ float As[2][BK][AP];
    __shared__ float Ws[2][BK][AP];

    const float* A = (mode == 2) ? g_ctx : (mode == 0) ? g_xm : (mode == 3) ? g_h : Ain;

    int tid = threadIdx.x;
    int tx = tid & 15, ty = tid >> 4;
    int m0 = blockIdx.y * BM, n0 = blockIdx.x * BN;

    float acc[8][8];
#pragma unroll
    for (int i = 0; i < 8; ++i)
#pragma unroll
        for (int j = 0; j < 8; ++j) acc[i][j] = 0.f;

    int nt = K / BK;

    // tile loaders: 512 float4 per operand per tile, 2 per thread
    auto loadA = [&](int buf, int k0) {
#pragma unroll
        for (int h = 0; h < 2; ++h) {
            int f = tid + h * 256;
            int row = f >> 2, kq = (f & 3) * 4;
            float4 v = *(const float4*)(A + (size_t)(m0 + row) * K + k0 + kq);
            As[buf][kq + 0][row] = v.x;
            As[buf][kq + 1][row] = v.y;
            As[buf][kq + 2][row] = v.z;
            As[buf][kq + 3][row] = v.w;
        }
    };
    auto loadW = [&](int buf, int k0) {
#pragma unroll
        for (int h = 0; h < 2; ++h) {
            int f = tid + h * 256;
            int row = f >> 2, kq = (f & 3) * 4;
            float4 v = *(const float4*)(W + (size_t)(n0 + row) * K + k0 + kq);
            Ws[buf][kq + 0][row] = v.x;
            Ws[buf][kq + 1][row] = v.y;
            Ws[buf][kq + 2][row] = v.z;
            Ws[buf][kq + 3][row] = v.w;
        }
    };

    loadA(0, 0);
    loadW(0, 0);
    __syncthreads();

    int buf = 0;
    for (int t = 0; t < nt; ++t) {
        if (t + 1 < nt) {
            loadA(buf ^ 1, (t + 1) * BK);
            loadW(buf ^ 1, (t + 1) * BK);
        }
#pragma unroll
        for (int k = 0; k < BK; ++k) {
            float ra[8], rw[8];
            *(float4*)(ra)     = *(const float4*)&As[buf][k][ty * 8];
            *(float4*)(ra + 4) = *(const float4*)&As[buf][k][ty * 8 + 4];
            *(float4*)(rw)     = *(const float4*)&Ws[buf][k][tx * 8];
            *(float4*)(rw + 4) = *(const float4*)&Ws[buf][k][tx * 8 + 4];
#pragma unroll
            for (int i = 0; i < 8; ++i)
#pragma unroll
                for (int j = 0; j < 8; ++j) acc[i][j] += ra[i] * rw[j];
        }
        __syncthreads();
        buf ^= 1;
    }

    // epilogue
#pragma unroll
    for (int i = 0; i < 8; ++i) {
        int m = m0 + ty * 8 + i;
        int b = m >> 10, n = m & 1023;
#pragma unroll
        for (int j = 0; j < 8; ++j) {
            int col = n0 + tx * 8 + j;
            float v = acc[i][j] + bias[col];
            if (mode == 0) {
                g_h[(size_t)m * Ncol + col] = v;
            } else if (mode == 2) {
                g_xm[(size_t)m * 2048 + 1024 + col] = v;
            } else if (mode == 3) {
                Cout[(size_t)m * Ncol + col] = v + resid[(size_t)m * Ncol + col];
            } else { // mode 1: QKV scatter
                int h = col / 192;
                int rem = col - h * 192;
                int d = rem / 3;
                int s = rem - d * 3;
                size_t di = (((size_t)(b * HH + h)) * NN + n) * HDIM + d;
                if (s == 0) g_q[di] = v;
                else if (s == 1) g_k[di] = v;
                else g_v[di] = v;
            }
        }
    }
}

// ---------------------------------------------------------------------------
// RoPE in-place on g_q and g_k.  encoding: [2, B, 1, N, HD]
// out[even d]  = t[d]*cos[d]   - t[d+1]*sin[d]
// out[odd d+1] = t[d+1]*cos[d+1] + t[d]*sin[d+1]
// ---------------------------------------------------------------------------
__global__ void rope_kernel(const float* __restrict__ enc)
{
    const int PH = BB * HH * NN * HDIM / 2; // pairs per tensor
    int p = blockIdx.x * blockDim.x + threadIdx.x;
    if (p >= 2 * PH) return;
    float* t = (p < PH) ? g_q : g_k;
    int pp = (p < PH) ? p : p - PH;
    int e = pp * 2;
    int d = e & 63;
    int n = (e >> 6) & 1023;
    int bh = e >> 16;
    int b = bh >> 4;
    float t0 = t[e], t1 = t[e + 1];
    size_t eb = ((size_t)(b * NN + n)) * HDIM + d;
    const int SINOFF = BB * NN * HDIM;
    float c0 = enc[eb], c1 = enc[eb + 1];
    float s0 = enc[eb + SINOFF], s1 = enc[eb + SINOFF + 1];
    t[e]     = t0 * c0 - t1 * s0;
    t[e + 1] = t1 * c1 + t0 * s1;
}

// copy x into first half of concat buffer
__global__ void copyx_kernel(const float* __restrict__ x)
{
    int i = blockIdx.x * 256 + threadIdx.x;   // float4 index, total 1048576
    float4 v = ((const float4*)x)[i];
    int m = i >> 8;
    int c = i & 255;
    ((float4*)g_xm)[(size_t)m * 512 + c] = v;
}

// ---------------------------------------------------------------------------
// Flash attention: per (b,h), 64-query tiles, 32-key tiles, online softmax.
// ctx written in [B,N,H,HD] (= [B,N,D]) layout.
// ---------------------------------------------------------------------------
__global__ __launch_bounds__(256) void attn_kernel()
{
    __shared__ float Qs[64][68];
    __shared__ float Ks[32][68];
    __shared__ float Vs[32][64];

    int bh = blockIdx.y;            // b*H + h
    int qt = blockIdx.x;            // query tile (16)
    int tid = threadIdx.x;
    int lane = tid & 31;
    int qr = tid >> 2;              // query row 0..63
    int sub = tid & 3;              // quad member

    const float* qbase = g_q + (size_t)bh * NN * HDIM + (size_t)qt * 64 * HDIM;
    const float* kbase = g_k + (size_t)bh * NN * HDIM;
    const float* vbase = g_v + (size_t)bh * NN * HDIM;
    const float scale = 0.125f;     // HD^-0.5

    // load Q (scaled): 1024 float4, 4 per thread
#pragma unroll
    for (int h = 0; h < 4; ++h) {
        int f = tid + h * 256;
        int r = f >> 4, cq = (f & 15) * 4;
        float4 v = *(const float4*)(qbase + (size_t)r * HDIM + cq);
        Qs[r][cq + 0] = v.x * scale;
        Qs[r][cq + 1] = v.y * scale;
        Qs[r][cq + 2] = v.z * scale;
        Qs[r][cq + 3] = v.w * scale;
    }

    float m_i = -1e30f, l_i = 0.f;
    float O[16];
#pragma unroll
    for (int i = 0; i < 16; ++i) O[i] = 0.f;
    __syncthreads();

    for (int kt = 0; kt < 32; ++kt) {
        const float* kb = kbase + (size_t)kt * 32 * HDIM;
        const float* vb = vbase + (size_t)kt * 32 * HDIM;
#pragma unroll
        for (int h = 0; h < 2; ++h) {
            int f = tid + h * 256;
            int r = f >> 4, cq = (f & 15) * 4;
            float4 kv = *(const float4*)(kb + (size_t)r * HDIM + cq);
            Ks[r][cq + 0] = kv.x; Ks[r][cq + 1] = kv.y;
            Ks[r][cq + 2] = kv.z; Ks[r][cq + 3] = kv.w;
            float4 vv = *(const float4*)(vb + (size_t)r * HDIM + cq);
            *(float4*)&Vs[r][cq] = vv;
        }
        __syncthreads();

        // S = Q K^T for this tile; thread owns columns c = i*4 + sub
        float s[8];
#pragma unroll
        for (int i = 0; i < 8; ++i) s[i] = 0.f;
#pragma unroll
        for (int d0 = 0; d0 < 64; d0 += 16) {
            float q0[16];
            *(float4*)(q0)      = *(const float4*)&Qs[qr][d0];
            *(float4*)(q0 + 4)  = *(const float4*)&Qs[qr][d0 + 4];
            *(float4*)(q0 + 8)  = *(const float4*)&Qs[qr][d0 + 8];
            *(float4*)(q0 + 12) = *(const float4*)&Qs[qr][d0 + 12];
#pragma unroll
            for (int i = 0; i < 8; ++i) {
                int c = i * 4 + sub;
                const float* kr = &Ks[c][d0];
                float4 k0 = *(const float4*)(kr);
                float4 k1 = *(const float4*)(kr + 4);
                float4 k2 = *(const float4*)(kr + 8);
                float4 k3 = *(const float4*)(kr + 12);
                s[i] += q0[0] * k0.x + q0[1] * k0.y + q0[2] * k0.z + q0[3] * k0.w
                      + q0[4] * k1.x + q0[5] * k1.y + q0[6] * k1.z + q0[7] * k1.w
                      + q0[8] * k2.x + q0[9] * k2.y + q0[10] * k2.z + q0[11] * k2.w
                      + q0[12] * k3.x + q0[13] * k3.y + q0[14] * k3.z + q0[15] * k3.w;
            }
        }

        // online softmax update (reduce across quad)
        float tm = s[0];
#pragma unroll
        for (int i = 1; i < 8; ++i) tm = fmaxf(tm, s[i]);
        tm = fmaxf(tm, __shfl_xor_sync(0xffffffffu, tm, 1));
        tm = fmaxf(tm, __shfl_xor_sync(0xffffffffu, tm, 2));
        float m_new = fmaxf(m_i, tm);
        float alpha = __expf(m_i - m_new);

        float p[8];
        float ps = 0.f;
#pragma unroll
        for (int i = 0; i < 8; ++i) { p[i] = __expf(s[i] - m_new); ps += p[i]; }
        ps += __shfl_xor_sync(0xffffffffu, ps, 1);
        ps += __shfl_xor_sync(0xffffffffu, ps, 2);
        l_i = l_i * alpha + ps;
        m_i = m_new;
#pragma unroll
        for (int i = 0; i < 16; ++i) O[i] *= alpha;

        // O += P @ V   (share p across quad via shuffle)
#pragma unroll
        for (int c = 0; c < 32; ++c) {
            float pv = __shfl_sync(0xffffffffu, p[c >> 2], (lane & ~3) | (c & 3));
            const float* vr = &Vs[c][sub * 16];
            float4 v0 = *(const float4*)(vr);
            float4 v1 = *(const float4*)(vr + 4);
            float4 v2 = *(const float4*)(vr + 8);
            float4 v3 = *(const float4*)(vr + 12);
            O[0]  += pv * v0.x; O[1]  += pv * v0.y; O[2]  += pv * v0.z; O[3]  += pv * v0.w;
            O[4]  += pv * v1.x; O[5]  += pv * v1.y; O[6]  += pv * v1.z; O[7]  += pv * v1.w;
            O[8]  += pv * v2.x; O[9]  += pv * v2.y; O[10] += pv * v2.z; O[11] += pv * v2.w;
            O[12] += pv * v3.x; O[13] += pv * v3.y; O[14] += pv * v3.z; O[15] += pv * v3.w;
        }
        __syncthreads();
    }

    float inv = 1.f / l_i;
#pragma unroll
    for (int i = 0; i < 16; ++i) O[i] *= inv;

    int b = bh >> 4, h = bh & 15;
    int nq = qt * 64 + qr;
    float* dst = g_ctx + (((size_t)(b * NN + nq)) * HH + h) * HDIM + sub * 16;
    *(float4*)(dst)      = *(float4*)(O);
    *(float4*)(dst + 4)  = *(float4*)(O + 4);
    *(float4*)(dst + 8)  = *(float4*)(O + 8);
    *(float4*)(dst + 12) = *(float4*)(O + 12);
}

// ---------------------------------------------------------------------------
// LayerNorm(2048) + exact GELU, in-place on g_h. One block per row.
// ---------------------------------------------------------------------------
__global__ __launch_bounds__(256) void ln_gelu_kernel(
    const float* __restrict__ lng, const float* __restrict__ lnb)
{
    int row = blockIdx.x;
    float* hr = g_h + (size_t)row * 2048;
    int tid = threadIdx.x;
    float v[8];
    float s = 0.f, s2 = 0.f;
#pragma unroll
    for (int i = 0; i < 8; ++i) {
        float t = hr[tid + i * 256];
        v[i] = t; s += t; s2 += t * t;
    }
#pragma unroll
    for (int o = 16; o; o >>= 1) {
        s  += __shfl_xor_sync(0xffffffffu, s,  o);
        s2 += __shfl_xor_sync(0xffffffffu, s2, o);
    }
    __shared__ float rs[8], rs2[8];
    __shared__ float sm, si;
    int wid = tid >> 5, lane = tid & 31;
    if (!lane) { rs[wid] = s; rs2[wid] = s2; }
    __syncthreads();
    if (tid == 0) {
        float S = 0.f, S2 = 0.f;
#pragma unroll
        for (int i = 0; i < 8; ++i) { S += rs[i]; S2 += rs2[i]; }
        float mean = S * (1.f / 2048.f);
        float var = S2 * (1.f / 2048.f) - mean * mean;
        sm = mean;
        si = rsqrtf(var + 1e-5f);
    }
    __syncthreads();
    float mean = sm, inv = si;
#pragma unroll
    for (int i = 0; i < 8; ++i) {
        int col = tid + i * 256;
        float t = (v[i] - mean) * inv * lng[col] + lnb[col];
        t = 0.5f * t * (1.f + erff(t * 0.70710678118654752f));
        hr[col] = t;
    }
}

// ---------------------------------------------------------------------------
extern "C" void kernel_launch(void* const* d_in, const int* in_sizes, int n_in,
                              void* d_out, int out_size)
{
    const float* x       = (const float*)d_in[0];
    const float* enc     = (const float*)d_in[1];
    const float* Wqkv_w  = (const float*)d_in[2];
    const float* Wqkv_b  = (const float*)d_in[3];
    const float* out_w   = (const float*)d_in[4];
    const float* out_b   = (const float*)d_in[5];
    const float* ffn1_w  = (const float*)d_in[6];
    const float* ffn1_b  = (const float*)d_in[7];
    const float* ln_g    = (const float*)d_in[8];
    const float* ln_b    = (const float*)d_in[9];
    const float* ffn2_w  = (const float*)d_in[10];
    const float* ffn2_b  = (const float*)d_in[11];
    float* out = (float*)d_out;

    // 1) QKV projection + scatter to q/k/v   (M=4096, N=3072, K=1024)
    gemm_kernel<<<dim3(3072 / BN, MROWS / BM), 256>>>(
        x, Wqkv_w, Wqkv_b, nullptr, nullptr, MROWS, 3072, 1024, 1);

    // 2) RoPE on q and k
    rope_kernel<<<(2 * BB * HH * NN * HDIM / 2 + 255) / 256, 256>>>(enc);

    // 3) copy x into concat buffer (independent of 1/2, but serialized stream is fine)
    copyx_kernel<<<(MROWS * DD / 4) / 256, 256>>>(x);

    // 4) attention -> g_ctx [B,N,D]
    attn_kernel<<<dim3(NN / 64, BB * HH), 256>>>();

    // 5) out projection -> g_xm[:,1024:2048]   (M=4096, N=1024, K=1024)
    gemm_kernel<<<dim3(1024 / BN, MROWS / BM), 256>>>(
        nullptr, out_w, out_b, nullptr, nullptr, MROWS, 1024, 1024, 2);

    // 6) FFN1 -> g_h   (M=4096, N=2048, K=2048)
    gemm_kernel<<<dim3(2048 / BN, MROWS / BM), 256>>>(
        nullptr, ffn1_w, ffn1_b, nullptr, nullptr, MROWS, 2048, 2048, 0);

    // 7) LayerNorm + GELU in-place
    ln_gelu_kernel<<<MROWS, 256>>>(ln_g, ln_b);

    // 8) FFN2 + residual -> d_out   (M=4096, N=1024, K=2048)
    gemm_kernel<<<dim3(1024 / BN, MROWS / BM), 256>>>(
        x, ffn2_w, ffn2_b, out, x, MROWS, 1024, 2048, 3);
}

// round 2
// speedup vs baseline: 1.5450x; 1.5450x over previous
#include <cuda_runtime.h>
#include <math.h>
#include <stdint.h>

// Problem constants
#define BB 4
#define NN 1024
#define DD 1024
#define HH 16
#define HDIM 64
#define MROWS (BB * NN)          // 4096

// Scratch (device globals; no allocations allowed)
__device__ float g_q[BB * HH * NN * HDIM];   // [B,H,N,HD]
__device__ float g_k[BB * HH * NN * HDIM];
__device__ float g_v[BB * HH * NN * HDIM];
__device__ float g_ctx[BB * NN * DD];        // [B,N,D] (H,HD interleaved = D)
__device__ float g_xm[MROWS * 2 * DD];       // concat([x, message]) rows of 2048
__device__ float g_h[MROWS * 2 * DD];        // FFN hidden, rows of 2048

// ---------------------------------------------------------------------------
// TF32 tensor-core GEMM:  C[M,Ncol] = A[M,K] @ W[Ncol,K]^T + bias
// mma.sync.m16n8k8 tf32, fp32 accumulate.
// mode 0: A=g_xm   -> g_h                      (FFN1)
// mode 1: A=Ain(x) -> scatter to g_q/g_k/g_v   (QKV)
// mode 2: A=g_ctx  -> g_xm[:,1024:2048]        (out-proj)
// mode 3: A=g_h    -> Cout = resid + result    (FFN2 + residual)
// ---------------------------------------------------------------------------
#define BM 128
#define BN 128
#define BK 16
#define APITCH 20   // floats; (20*r + k) mod 32 distinct for r in [0,8), k in [0,4)

__device__ __forceinline__ float to_tf32(float x) {
    uint32_t u;
    asm("cvt.rna.tf32.f32 %0, %1;" : "=r"(u) : "f"(x));
    return __uint_as_float(u);
}

__device__ __forceinline__ void mma_tf32(float* c, const uint32_t* a, const uint32_t* b) {
    asm volatile(
        "mma.sync.aligned.m16n8k8.row.col.f32.tf32.tf32.f32 "
        "{%0,%1,%2,%3}, {%4,%5,%6,%7}, {%8,%9}, {%0,%1,%2,%3};"
        : "+f"(c[0]), "+f"(c[1]), "+f"(c[2]), "+f"(c[3])
        : "r"(a[0]), "r"(a[1]), "r"(a[2]), "r"(a[3]), "r"(b[0]), "r"(b[1]));
}

__global__ __launch_bounds__(256) void gemm_kernel(
    const float* __restrict__ Ain, const float* __restrict__ W,
    const float* __restrict__ bias, float* __restrict__ Cout,
    const float* __restrict__ resid, int M, int Ncol, int K, int mode)
{
    __shared__ float As[2][BM][APITCH];   // [row][k]
    __shared__ float Ws[2][BN][APITCH];   // [col][k]

    const float* A = (mode == 2) ? g_ctx : (mode == 0) ? g_xm : (mode == 3) ? g_h : Ain;

    int tid = threadIdx.x;
    int lane = tid & 31;
    int wid = tid >> 5;
    int wm = wid >> 2;   // 0..1 -> 64 rows
    int wn = wid & 3;    // 0..3 -> 32 cols
    int m0 = blockIdx.y * BM, n0 = blockIdx.x * BN;

    float acc[4][4][4];
#pragma unroll
    for (int i = 0; i < 4; ++i)
#pragma unroll
        for (int j = 0; j < 4; ++j)
#pragma unroll
            for (int r = 0; r < 4; ++r) acc[i][j][r] = 0.f;

    int nt = K / BK;

    float4 ra[2], rw[2];

    auto ldg = [&](int k0) {
#pragma unroll
        for (int h = 0; h < 2; ++h) {
            int idx = tid + h * 256;
            int row = idx >> 2, kq = (idx & 3) * 4;
            ra[h] = *(const float4*)(A + (size_t)(m0 + row) * K + k0 + kq);
            rw[h] = *(const float4*)(W + (size_t)(n0 + row) * K + k0 + kq);
        }
    };
    auto sts = [&](int buf) {
#pragma unroll
        for (int h = 0; h < 2; ++h) {
            int idx = tid + h * 256;
            int row = idx >> 2, kq = (idx & 3) * 4;
            float4 ca = make_float4(to_tf32(ra[h].x), to_tf32(ra[h].y),
                                    to_tf32(ra[h].z), to_tf32(ra[h].w));
            float4 cw = make_float4(to_tf32(rw[h].x), to_tf32(rw[h].y),
                                    to_tf32(rw[h].z), to_tf32(rw[h].w));
            *(float4*)&As[buf][row][kq] = ca;
            *(float4*)&Ws[buf][row][kq] = cw;
        }
    };

    ldg(0);
    sts(0);
    __syncthreads();

    int buf = 0;
    for (int t = 0; t < nt; ++t) {
        if (t + 1 < nt) ldg((t + 1) * BK);

#pragma unroll
        for (int kk = 0; kk < BK; kk += 8) {
            int ko = kk + (lane & 3);
            uint32_t af[4][4], bf[4][2];
#pragma unroll
            for (int tm = 0; tm < 4; ++tm) {
                int r = wm * 64 + tm * 16 + (lane >> 2);
                af[tm][0] = __float_as_uint(As[buf][r][ko]);
                af[tm][1] = __float_as_uint(As[buf][r + 8][ko]);
                af[tm][2] = __float_as_uint(As[buf][r][ko + 4]);
                af[tm][3] = __float_as_uint(As[buf][r + 8][ko + 4]);
            }
#pragma unroll
            for (int tn = 0; tn < 4; ++tn) {
                int c = wn * 32 + tn * 8 + (lane >> 2);
                bf[tn][0] = __float_as_uint(Ws[buf][c][ko]);
                bf[tn][1] = __float_as_uint(Ws[buf][c][ko + 4]);
            }
#pragma unroll
            for (int tm = 0; tm < 4; ++tm)
#pragma unroll
                for (int tn = 0; tn < 4; ++tn)
                    mma_tf32(acc[tm][tn], af[tm], bf[tn]);
        }

        if (t + 1 < nt) sts(buf ^ 1);
        __syncthreads();
        buf ^= 1;
    }

    // epilogue: c0:(r, 2q) c1:(r, 2q+1) c2:(r+8, 2q) c3:(r+8, 2q+1)
    int rbase = m0 + wm * 64 + (lane >> 2);
    int cbase = n0 + wn * 32 + 2 * (lane & 3);
#pragma unroll
    for (int tm = 0; tm < 4; ++tm) {
#pragma unroll
        for (int tn = 0; tn < 4; ++tn) {
#pragma unroll
            for (int r = 0; r < 4; ++r) {
                int m = rbase + tm * 16 + ((r >> 1) ? 8 : 0);
                int col = cbase + tn * 8 + (r & 1);
                float v = acc[tm][tn][r] + bias[col];
                int b = m >> 10, n = m & 1023;
                if (mode == 0) {
                    g_h[(size_t)m * Ncol + col] = v;
                } else if (mode == 2) {
                    g_xm[(size_t)m * 2048 + 1024 + col] = v;
                } else if (mode == 3) {
                    Cout[(size_t)m * Ncol + col] = v + resid[(size_t)m * Ncol + col];
                } else { // mode 1: QKV scatter
                    int h = col / 192;
                    int rem = col - h * 192;
                    int d = rem / 3;
                    int s = rem - d * 3;
                    size_t di = (((size_t)(b * HH + h)) * NN + n) * HDIM + d;
                    if (s == 0) g_q[di] = v;
                    else if (s == 1) g_k[di] = v;
                    else g_v[di] = v;
                }
            }
        }
    }
}

// ---------------------------------------------------------------------------
// RoPE in-place on g_q and g_k.  encoding: [2, B, 1, N, HD]
// ---------------------------------------------------------------------------
__global__ void rope_kernel(const float* __restrict__ enc)
{
    const int PH = BB * HH * NN * HDIM / 2; // pairs per tensor
    int p = blockIdx.x * blockDim.x + threadIdx.x;
    if (p >= 2 * PH) return;
    float* t = (p < PH) ? g_q : g_k;
    int pp = (p < PH) ? p : p - PH;
    int e = pp * 2;
    int d = e & 63;
    int n = (e >> 6) & 1023;
    int bh = e >> 16;
    int b = bh >> 4;
    float t0 = t[e], t1 = t[e + 1];
    size_t eb = ((size_t)(b * NN + n)) * HDIM + d;
    const int SINOFF = BB * NN * HDIM;
    float c0 = enc[eb], c1 = enc[eb + 1];
    float s0 = enc[eb + SINOFF], s1 = enc[eb + SINOFF + 1];
    t[e]     = t0 * c0 - t1 * s0;
    t[e + 1] = t1 * c1 + t0 * s1;
}

// copy x into first half of concat buffer
__global__ void copyx_kernel(const float* __restrict__ x)
{
    int i = blockIdx.x * 256 + threadIdx.x;   // float4 index, total 1048576
    float4 v = ((const float4*)x)[i];
    int m = i >> 8;
    int c = i & 255;
    ((float4*)g_xm)[(size_t)m * 512 + c] = v;
}

// ---------------------------------------------------------------------------
// Flash attention: per (b,h), 64-query tiles, 32-key tiles, online softmax.
// ---------------------------------------------------------------------------
__global__ __launch_bounds__(256) void attn_kernel()
{
    __shared__ float Qs[64][68];
    __shared__ float Ks[32][68];
    __shared__ float Vs[32][64];

    int bh = blockIdx.y;
    int qt = blockIdx.x;
    int tid = threadIdx.x;
    int lane = tid & 31;
    int qr = tid >> 2;
    int sub = tid & 3;

    const float* qbase = g_q + (size_t)bh * NN * HDIM + (size_t)qt * 64 * HDIM;
    const float* kbase = g_k + (size_t)bh * NN * HDIM;
    const float* vbase = g_v + (size_t)bh * NN * HDIM;
    const float scale = 0.125f;

#pragma unroll
    for (int h = 0; h < 4; ++h) {
        int f = tid + h * 256;
        int r = f >> 4, cq = (f & 15) * 4;
        float4 v = *(const float4*)(qbase + (size_t)r * HDIM + cq);
        Qs[r][cq + 0] = v.x * scale;
        Qs[r][cq + 1] = v.y * scale;
        Qs[r][cq + 2] = v.z * scale;
        Qs[r][cq + 3] = v.w * scale;
    }

    float m_i = -1e30f, l_i = 0.f;
    float O[16];
#pragma unroll
    for (int i = 0; i < 16; ++i) O[i] = 0.f;
    __syncthreads();

    for (int kt = 0; kt < 32; ++kt) {
        const float* kb = kbase + (size_t)kt * 32 * HDIM;
        const float* vb = vbase + (size_t)kt * 32 * HDIM;
#pragma unroll
        for (int h = 0; h < 2; ++h) {
            int f = tid + h * 256;
            int r = f >> 4, cq = (f & 15) * 4;
            float4 kv = *(const float4*)(kb + (size_t)r * HDIM + cq);
            Ks[r][cq + 0] = kv.x; Ks[r][cq + 1] = kv.y;
            Ks[r][cq + 2] = kv.z; Ks[r][cq + 3] = kv.w;
            float4 vv = *(const float4*)(vb + (size_t)r * HDIM + cq);
            *(float4*)&Vs[r][cq] = vv;
        }
        __syncthreads();

        float s[8];
#pragma unroll
        for (int i = 0; i < 8; ++i) s[i] = 0.f;
#pragma unroll
        for (int d0 = 0; d0 < 64; d0 += 16) {
            float q0[16];
            *(float4*)(q0)      = *(const float4*)&Qs[qr][d0];
            *(float4*)(q0 + 4)  = *(const float4*)&Qs[qr][d0 + 4];
            *(float4*)(q0 + 8)  = *(const float4*)&Qs[qr][d0 + 8];
            *(float4*)(q0 + 12) = *(const float4*)&Qs[qr][d0 + 12];
#pragma unroll
            for (int i = 0; i < 8; ++i) {
                int c = i * 4 + sub;
                const float* kr = &Ks[c][d0];
                float4 k0 = *(const float4*)(kr);
                float4 k1 = *(const float4*)(kr + 4);
                float4 k2 = *(const float4*)(kr + 8);
                float4 k3 = *(const float4*)(kr + 12);
                s[i] += q0[0] * k0.x + q0[1] * k0.y + q0[2] * k0.z + q0[3] * k0.w
                      + q0[4] * k1.x + q0[5] * k1.y + q0[6] * k1.z + q0[7] * k1.w
                      + q0[8] * k2.x + q0[9] * k2.y + q0[10] * k2.z + q0[11] * k2.w
                      + q0[12] * k3.x + q0[13] * k3.y + q0[14] * k3.z + q0[15] * k3.w;
            }
        }

        float tm = s[0];
#pragma unroll
        for (int i = 1; i < 8; ++i) tm = fmaxf(tm, s[i]);
        tm = fmaxf(tm, __shfl_xor_sync(0xffffffffu, tm, 1));
        tm = fmaxf(tm, __shfl_xor_sync(0xffffffffu, tm, 2));
        float m_new = fmaxf(m_i, tm);
        float alpha = __expf(m_i - m_new);

        float p[8];
        float ps = 0.f;
#pragma unroll
        for (int i = 0; i < 8; ++i) { p[i] = __expf(s[i] - m_new); ps += p[i]; }
        ps += __shfl_xor_sync(0xffffffffu, ps, 1);
        ps += __shfl_xor_sync(0xffffffffu, ps, 2);
        l_i = l_i * alpha + ps;
        m_i = m_new;
#pragma unroll
        for (int i = 0; i < 16; ++i) O[i] *= alpha;

#pragma unroll
        for (int c = 0; c < 32; ++c) {
            float pv = __shfl_sync(0xffffffffu, p[c >> 2], (lane & ~3) | (c & 3));
            const float* vr = &Vs[c][sub * 16];
            float4 v0 = *(const float4*)(vr);
            float4 v1 = *(const float4*)(vr + 4);
            float4 v2 = *(const float4*)(vr + 8);
            float4 v3 = *(const float4*)(vr + 12);
            O[0]  += pv * v0.x; O[1]  += pv * v0.y; O[2]  += pv * v0.z; O[3]  += pv * v0.w;
            O[4]  += pv * v1.x; O[5]  += pv * v1.y; O[6]  += pv * v1.z; O[7]  += pv * v1.w;
            O[8]  += pv * v2.x; O[9]  += pv * v2.y; O[10] += pv * v2.z; O[11] += pv * v2.w;
            O[12] += pv * v3.x; O[13] += pv * v3.y; O[14] += pv * v3.z; O[15] += pv * v3.w;
        }
        __syncthreads();
    }

    float inv = 1.f / l_i;
#pragma unroll
    for (int i = 0; i < 16; ++i) O[i] *= inv;

    int b = bh >> 4, h = bh & 15;
    int nq = qt * 64 + qr;
    float* dst = g_ctx + (((size_t)(b * NN + nq)) * HH + h) * HDIM + sub * 16;
    *(float4*)(dst)      = *(float4*)(O);
    *(float4*)(dst + 4)  = *(float4*)(O + 4);
    *(float4*)(dst + 8)  = *(float4*)(O + 8);
    *(float4*)(dst + 12) = *(float4*)(O + 12);
}

// ---------------------------------------------------------------------------
// LayerNorm(2048) + exact GELU, in-place on g_h.
// ---------------------------------------------------------------------------
__global__ __launch_bounds__(256) void ln_gelu_kernel(
    const float* __restrict__ lng, const float* __restrict__ lnb)
{
    int row = blockIdx.x;
    float* hr = g_h + (size_t)row * 2048;
    int tid = threadIdx.x;
    float v[8];
    float s = 0.f, s2 = 0.f;
#pragma unroll
    for (int i = 0; i < 8; ++i) {
        float t = hr[tid + i * 256];
        v[i] = t; s += t; s2 += t * t;
    }
#pragma unroll
    for (int o = 16; o; o >>= 1) {
        s  += __shfl_xor_sync(0xffffffffu, s,  o);
        s2 += __shfl_xor_sync(0xffffffffu, s2, o);
    }
    __shared__ float rs[8], rs2[8];
    __shared__ float sm, si;
    int wid = tid >> 5, lane = tid & 31;
    if (!lane) { rs[wid] = s; rs2[wid] = s2; }
    __syncthreads();
    if (tid == 0) {
        float S = 0.f, S2 = 0.f;
#pragma unroll
        for (int i = 0; i < 8; ++i) { S += rs[i]; S2 += rs2[i]; }
        float mean = S * (1.f / 2048.f);
        float var = S2 * (1.f / 2048.f) - mean * mean;
        sm = mean;
        si = rsqrtf(var + 1e-5f);
    }
    __syncthreads();
    float mean = sm, inv = si;
#pragma unroll
    for (int i = 0; i < 8; ++i) {
        int col = tid + i * 256;
        float t = (v[i] - mean) * inv * lng[col] + lnb[col];
        t = 0.5f * t * (1.f + erff(t * 0.70710678118654752f));
        hr[col] = t;
    }
}

// ---------------------------------------------------------------------------
extern "C" void kernel_launch(void* const* d_in, const int* in_sizes, int n_in,
                              void* d_out, int out_size)
{
    const float* x       = (const float*)d_in[0];
    const float* enc     = (const float*)d_in[1];
    const float* Wqkv_w  = (const float*)d_in[2];
    const float* Wqkv_b  = (const float*)d_in[3];
    const float* out_w   = (const float*)d_in[4];
    const float* out_b   = (const float*)d_in[5];
    const float* ffn1_w  = (const float*)d_in[6];
    const float* ffn1_b  = (const float*)d_in[7];
    const float* ln_g    = (const float*)d_in[8];
    const float* ln_b    = (const float*)d_in[9];
    const float* ffn2_w  = (const float*)d_in[10];
    const float* ffn2_b  = (const float*)d_in[11];
    float* out = (float*)d_out;

    // 1) QKV projection + scatter to q/k/v   (M=4096, N=3072, K=1024)
    gemm_kernel<<<dim3(3072 / BN, MROWS / BM), 256>>>(
        x, Wqkv_w, Wqkv_b, nullptr, nullptr, MROWS, 3072, 1024, 1);

    // 2) RoPE on q and k
    rope_kernel<<<(2 * BB * HH * NN * HDIM / 2 + 255) / 256, 256>>>(enc);

    // 3) copy x into concat buffer
    copyx_kernel<<<(MROWS * DD / 4) / 256, 256>>>(x);

    // 4) attention -> g_ctx [B,N,D]
    attn_kernel<<<dim3(NN / 64, BB * HH), 256>>>();

    // 5) out projection -> g_xm[:,1024:2048]   (M=4096, N=1024, K=1024)
    gemm_kernel<<<dim3(1024 / BN, MROWS / BM), 256>>>(
        nullptr, out_w, out_b, nullptr, nullptr, MROWS, 1024, 1024, 2);

    // 6) FFN1 -> g_h   (M=4096, N=2048, K=2048)
    gemm_kernel<<<dim3(2048 / BN, MROWS / BM), 256>>>(
        nullptr, ffn1_w, ffn1_b, nullptr, nullptr, MROWS, 2048, 2048, 0);

    // 7) LayerNorm + GELU in-place
    ln_gelu_kernel<<<MROWS, 256>>>(ln_g, ln_b);

    // 8) FFN2 + residual -> d_out   (M=4096, N=1024, K=2048)
    gemm_kernel<<<dim3(1024 / BN, MROWS / BM), 256>>>(
        x, ffn2_w, ffn2_b, out, x, MROWS, 1024, 2048, 3);
}

// round 3
// speedup vs baseline: 3.4144x; 2.2100x over previous
#include <cuda_runtime.h>
#include <math.h>
#include <stdint.h>

// Problem constants
#define BB 4
#define NN 1024
#define DD 1024
#define HH 16
#define HDIM 64
#define MROWS (BB * NN)          // 4096

// Scratch (device globals; no allocations allowed)
__device__ float g_q[BB * HH * NN * HDIM];   // [B,H,N,HD]
__device__ float g_k[BB * HH * NN * HDIM];
__device__ float g_v[BB * HH * NN * HDIM];
__device__ float g_ctx[BB * NN * DD];        // [B,N,D] ([B,N,H,HD])
__device__ float g_xm[MROWS * 2 * DD];       // concat([x, message]) rows of 2048
__device__ float g_h[MROWS * 2 * DD];        // FFN hidden, rows of 2048

__device__ __forceinline__ uint32_t tf32bits(float x) {
    uint32_t u;
    asm("cvt.rna.tf32.f32 %0, %1;" : "=r"(u) : "f"(x));
    return u;
}
__device__ __forceinline__ float to_tf32(float x) {
    return __uint_as_float(tf32bits(x));
}
__device__ __forceinline__ void mma_tf32(float* c, const uint32_t* a, const uint32_t* b) {
    asm volatile(
        "mma.sync.aligned.m16n8k8.row.col.f32.tf32.tf32.f32 "
        "{%0,%1,%2,%3}, {%4,%5,%6,%7}, {%8,%9}, {%0,%1,%2,%3};"
        : "+f"(c[0]), "+f"(c[1]), "+f"(c[2]), "+f"(c[3])
        : "r"(a[0]), "r"(a[1]), "r"(a[2]), "r"(a[3]), "r"(b[0]), "r"(b[1]));
}

// ---------------------------------------------------------------------------
// TF32 tensor-core GEMM:  C[M,Ncol] = A[M,K] @ W[Ncol,K]^T + bias
// 128x128 block tile, 4 warps of 64x64, 128 threads.
// mode 0: A=g_xm   -> g_h                      (FFN1)
// mode 1: A=Ain(x) -> scatter to g_q/g_k/g_v   (QKV)
// mode 2: A=g_ctx  -> g_xm[:,1024:2048]        (out-proj)
// mode 3: A=g_h    -> Cout = resid + result    (FFN2 + residual)
// ---------------------------------------------------------------------------
#define BM 128
#define BN 128
#define BK 16
#define APITCH 20   // (20*r + k) mod 32 distinct for r in [0,8), k in [0,4)

__global__ __launch_bounds__(128) void gemm_kernel(
    const float* __restrict__ Ain, const float* __restrict__ W,
    const float* __restrict__ bias, float* __restrict__ Cout,
    const float* __restrict__ resid, int M, int Ncol, int K, int mode)
{
    __shared__ float As[2][BM][APITCH];   // [row][k]
    __shared__ float Ws[2][BN][APITCH];   // [col][k]

    const float* A = (mode == 2) ? g_ctx : (mode == 0) ? g_xm : (mode == 3) ? g_h : Ain;

    int tid = threadIdx.x;
    int lane = tid & 31;
    int wid = tid >> 5;
    int g = lane >> 2, t = lane & 3;
    int wm = wid >> 1;   // 0..1 -> 64 rows
    int wn = wid & 1;    // 0..1 -> 64 cols
    int m0 = blockIdx.y * BM, n0 = blockIdx.x * BN;

    float acc[4][8][4];
#pragma unroll
    for (int i = 0; i < 4; ++i)
#pragma unroll
        for (int j = 0; j < 8; ++j)
#pragma unroll
            for (int r = 0; r < 4; ++r) acc[i][j][r] = 0.f;

    int nt = K / BK;
    float4 ra[4], rw[4];

    auto ldg = [&](int k0) {
#pragma unroll
        for (int h = 0; h < 4; ++h) {
            int idx = tid + h * 128;
            int row = idx >> 2, kq = (idx & 3) * 4;
            ra[h] = *(const float4*)(A + (size_t)(m0 + row) * K + k0 + kq);
            rw[h] = *(const float4*)(W + (size_t)(n0 + row) * K + k0 + kq);
        }
    };
    auto sts = [&](int buf) {
#pragma unroll
        for (int h = 0; h < 4; ++h) {
            int idx = tid + h * 128;
            int row = idx >> 2, kq = (idx & 3) * 4;
            float4 ca = make_float4(to_tf32(ra[h].x), to_tf32(ra[h].y),
                                    to_tf32(ra[h].z), to_tf32(ra[h].w));
            float4 cw = make_float4(to_tf32(rw[h].x), to_tf32(rw[h].y),
                                    to_tf32(rw[h].z), to_tf32(rw[h].w));
            *(float4*)&As[buf][row][kq] = ca;
            *(float4*)&Ws[buf][row][kq] = cw;
        }
    };

    ldg(0);
    sts(0);
    __syncthreads();

    int buf = 0;
    for (int tt = 0; tt < nt; ++tt) {
        if (tt + 1 < nt) ldg((tt + 1) * BK);

#pragma unroll
        for (int kk = 0; kk < BK; kk += 8) {
            int ko = kk + t;
            uint32_t af[4][4], bf[8][2];
#pragma unroll
            for (int tm = 0; tm < 4; ++tm) {
                int r = wm * 64 + tm * 16 + g;
                af[tm][0] = __float_as_uint(As[buf][r][ko]);
                af[tm][1] = __float_as_uint(As[buf][r + 8][ko]);
                af[tm][2] = __float_as_uint(As[buf][r][ko + 4]);
                af[tm][3] = __float_as_uint(As[buf][r + 8][ko + 4]);
            }
#pragma unroll
            for (int tn = 0; tn < 8; ++tn) {
                int c = wn * 64 + tn * 8 + g;
                bf[tn][0] = __float_as_uint(Ws[buf][c][ko]);
                bf[tn][1] = __float_as_uint(Ws[buf][c][ko + 4]);
            }
#pragma unroll
            for (int tm = 0; tm < 4; ++tm)
#pragma unroll
                for (int tn = 0; tn < 8; ++tn)
                    mma_tf32(acc[tm][tn], af[tm], bf[tn]);
        }

        if (tt + 1 < nt) sts(buf ^ 1);
        __syncthreads();
        buf ^= 1;
    }

    // epilogue: c0:(r, 2t) c1:(r, 2t+1) c2:(r+8, 2t) c3:(r+8, 2t+1)
    int rbase = m0 + wm * 64 + g;
    int cbase = n0 + wn * 64 + 2 * t;
#pragma unroll
    for (int tm = 0; tm < 4; ++tm) {
#pragma unroll
        for (int tn = 0; tn < 8; ++tn) {
#pragma unroll
            for (int r = 0; r < 4; ++r) {
                int m = rbase + tm * 16 + ((r >> 1) ? 8 : 0);
                int col = cbase + tn * 8 + (r & 1);
                float v = acc[tm][tn][r] + bias[col];
                int b = m >> 10, n = m & 1023;
                if (mode == 0) {
                    g_h[(size_t)m * Ncol + col] = v;
                } else if (mode == 2) {
                    g_xm[(size_t)m * 2048 + 1024 + col] = v;
                } else if (mode == 3) {
                    Cout[(size_t)m * Ncol + col] = v + resid[(size_t)m * Ncol + col];
                } else { // mode 1: QKV scatter
                    int h = col / 192;
                    int rem = col - h * 192;
                    int d = rem / 3;
                    int s = rem - d * 3;
                    size_t di = (((size_t)(b * HH + h)) * NN + n) * HDIM + d;
                    if (s == 0) g_q[di] = v;
                    else if (s == 1) g_k[di] = v;
                    else g_v[di] = v;
                }
            }
        }
    }
}

// ---------------------------------------------------------------------------
// RoPE in-place on g_q and g_k.  encoding: [2, B, 1, N, HD]
// ---------------------------------------------------------------------------
__global__ void rope_kernel(const float* __restrict__ enc)
{
    const int PH = BB * HH * NN * HDIM / 2;
    int p = blockIdx.x * blockDim.x + threadIdx.x;
    if (p >= 2 * PH) return;
    float* t = (p < PH) ? g_q : g_k;
    int pp = (p < PH) ? p : p - PH;
    int e = pp * 2;
    int d = e & 63;
    int n = (e >> 6) & 1023;
    int bh = e >> 16;
    int b = bh >> 4;
    float t0 = t[e], t1 = t[e + 1];
    size_t eb = ((size_t)(b * NN + n)) * HDIM + d;
    const int SINOFF = BB * NN * HDIM;
    float c0 = enc[eb], c1 = enc[eb + 1];
    float s0 = enc[eb + SINOFF], s1 = enc[eb + SINOFF + 1];
    t[e]     = t0 * c0 - t1 * s0;
    t[e + 1] = t1 * c1 + t0 * s1;
}

// copy x into first half of concat buffer
__global__ void copyx_kernel(const float* __restrict__ x)
{
    int i = blockIdx.x * 256 + threadIdx.x;
    float4 v = ((const float4*)x)[i];
    int m = i >> 8;
    int c = i & 255;
    ((float4*)g_xm)[(size_t)m * 512 + c] = v;
}

// ---------------------------------------------------------------------------
// Flash attention on tensor cores (tf32 m16n8k8).
// Block: 128 query rows (8 warps x 16), key tiles of 64, online softmax.
// Q fragments in registers; K in Ks[key][hd]; V transposed in VsT[hd][key];
// P re-fragmented via intra-quad shuffles (no smem round-trip).
// ---------------------------------------------------------------------------
#define KP 68   // Ks pitch: bank = (4g + t) -> conflict-free fragment loads
#define VP 65   // VsT pitch: 2-way conflicts on loads/stores (accepted)

__global__ __launch_bounds__(256) void attn_kernel()
{
    __shared__ float Ks[64][KP];
    __shared__ float VsT[64][VP];

    int bh = blockIdx.y;
    int qt = blockIdx.x;
    int tid = threadIdx.x;
    int lane = tid & 31;
    int wid = tid >> 5;
    int g = lane >> 2, t = lane & 3;

    const float* qbase = g_q + (size_t)bh * NN * HDIM + (size_t)qt * 128 * HDIM;
    const float* kbase = g_k + (size_t)bh * NN * HDIM;
    const float* vbase = g_v + (size_t)bh * NN * HDIM;

    // Q fragments (pre-scaled): warp rows wid*16+g, wid*16+g+8; 8 hd-chunks
    uint32_t qf[8][4];
    {
        const float* q0 = qbase + (size_t)(wid * 16 + g) * HDIM;
        const float* q1 = q0 + 8 * HDIM;
#pragma unroll
        for (int kc = 0; kc < 8; ++kc) {
            int k0 = kc * 8 + t;
            qf[kc][0] = tf32bits(q0[k0] * 0.125f);
            qf[kc][1] = tf32bits(q1[k0] * 0.125f);
            qf[kc][2] = tf32bits(q0[k0 + 4] * 0.125f);
            qf[kc][3] = tf32bits(q1[k0 + 4] * 0.125f);
        }
    }

    float m0 = -1e30f, m1 = -1e30f, l0 = 0.f, l1 = 0.f;
    float O[8][4];
#pragma unroll
    for (int i = 0; i < 8; ++i)
#pragma unroll
        for (int r = 0; r < 4; ++r) O[i][r] = 0.f;

    const int sl0 = (lane & ~3) | (t >> 1);
    const int sl1 = sl0 + 2;

    for (int kt = 0; kt < 16; ++kt) {
        const float* kb = kbase + (size_t)kt * 64 * HDIM;
        const float* vb = vbase + (size_t)kt * 64 * HDIM;
#pragma unroll
        for (int h2 = 0; h2 < 4; ++h2) {
            int f = tid + h2 * 256;
            int r = f >> 4, cq = (f & 15) * 4;
            float4 kv = *(const float4*)(kb + (size_t)r * HDIM + cq);
            float4 ck = make_float4(to_tf32(kv.x), to_tf32(kv.y),
                                    to_tf32(kv.z), to_tf32(kv.w));
            *(float4*)&Ks[r][cq] = ck;
            float4 vv = *(const float4*)(vb + (size_t)r * HDIM + cq);
            VsT[cq + 0][r] = to_tf32(vv.x);
            VsT[cq + 1][r] = to_tf32(vv.y);
            VsT[cq + 2][r] = to_tf32(vv.z);
            VsT[cq + 3][r] = to_tf32(vv.w);
        }
        __syncthreads();

        // S = Q K^T  (16 rows x 64 key cols per warp)
        float S[8][4];
#pragma unroll
        for (int i = 0; i < 8; ++i)
#pragma unroll
            for (int r = 0; r < 4; ++r) S[i][r] = 0.f;
#pragma unroll
        for (int kc = 0; kc < 8; ++kc) {
#pragma unroll
            for (int ntile = 0; ntile < 8; ++ntile) {
                uint32_t bf[2];
                bf[0] = __float_as_uint(Ks[ntile * 8 + g][kc * 8 + t]);
                bf[1] = __float_as_uint(Ks[ntile * 8 + g][kc * 8 + t + 4]);
                mma_tf32(S[ntile], qf[kc], bf);
            }
        }

        // online softmax
        float tm0 = -1e30f, tm1 = -1e30f;
#pragma unroll
        for (int i = 0; i < 8; ++i) {
            tm0 = fmaxf(tm0, fmaxf(S[i][0], S[i][1]));
            tm1 = fmaxf(tm1, fmaxf(S[i][2], S[i][3]));
        }
        tm0 = fmaxf(tm0, __shfl_xor_sync(0xffffffffu, tm0, 1));
        tm0 = fmaxf(tm0, __shfl_xor_sync(0xffffffffu, tm0, 2));
        tm1 = fmaxf(tm1, __shfl_xor_sync(0xffffffffu, tm1, 1));
        tm1 = fmaxf(tm1, __shfl_xor_sync(0xffffffffu, tm1, 2));
        float mn0 = fmaxf(m0, tm0), mn1 = fmaxf(m1, tm1);
        float a0 = __expf(m0 - mn0), a1 = __expf(m1 - mn1);
        m0 = mn0; m1 = mn1;

        float ps0 = 0.f, ps1 = 0.f;
#pragma unroll
        for (int i = 0; i < 8; ++i) {
            float p0 = __expf(S[i][0] - mn0);
            float p1 = __expf(S[i][1] - mn0);
            float p2 = __expf(S[i][2] - mn1);
            float p3 = __expf(S[i][3] - mn1);
            ps0 += p0 + p1; ps1 += p2 + p3;
            S[i][0] = __uint_as_float(tf32bits(p0));
            S[i][1] = __uint_as_float(tf32bits(p1));
            S[i][2] = __uint_as_float(tf32bits(p2));
            S[i][3] = __uint_as_float(tf32bits(p3));
        }
        ps0 += __shfl_xor_sync(0xffffffffu, ps0, 1);
        ps0 += __shfl_xor_sync(0xffffffffu, ps0, 2);
        ps1 += __shfl_xor_sync(0xffffffffu, ps1, 1);
        ps1 += __shfl_xor_sync(0xffffffffu, ps1, 2);
        l0 = l0 * a0 + ps0;
        l1 = l1 * a1 + ps1;
#pragma unroll
        for (int i = 0; i < 8; ++i) {
            O[i][0] *= a0; O[i][1] *= a0; O[i][2] *= a1; O[i][3] *= a1;
        }

        // O += P @ V : per key chunk kc build A-frag of P via quad shuffles
#pragma unroll
        for (int kc = 0; kc < 8; ++kc) {
            float v00 = __shfl_sync(0xffffffffu, S[kc][0], sl0);
            float v01 = __shfl_sync(0xffffffffu, S[kc][1], sl0);
            float v10 = __shfl_sync(0xffffffffu, S[kc][2], sl0);
            float v11 = __shfl_sync(0xffffffffu, S[kc][3], sl0);
            float v20 = __shfl_sync(0xffffffffu, S[kc][0], sl1);
            float v21 = __shfl_sync(0xffffffffu, S[kc][1], sl1);
            float v30 = __shfl_sync(0xffffffffu, S[kc][2], sl1);
            float v31 = __shfl_sync(0xffffffffu, S[kc][3], sl1);
            uint32_t af[4];
            af[0] = __float_as_uint((t & 1) ? v01 : v00);
            af[1] = __float_as_uint((t & 1) ? v11 : v10);
            af[2] = __float_as_uint((t & 1) ? v21 : v20);
            af[3] = __float_as_uint((t & 1) ? v31 : v30);
#pragma unroll
            for (int ntile = 0; ntile < 8; ++ntile) {
                uint32_t bf[2];
                bf[0] = __float_as_uint(VsT[ntile * 8 + g][kc * 8 + t]);
                bf[1] = __float_as_uint(VsT[ntile * 8 + g][kc * 8 + t + 4]);
                mma_tf32(O[ntile], af, bf);
            }
        }
        __syncthreads();
    }

    float i0 = 1.f / l0, i1 = 1.f / l1;
    int b = bh >> 4, h = bh & 15;
    int r0 = qt * 128 + wid * 16 + g;
    float* d0 = g_ctx + (((size_t)(b * NN + r0)) * HH + h) * HDIM;
    float* d1 = g_ctx + (((size_t)(b * NN + r0 + 8)) * HH + h) * HDIM;
#pragma unroll
    for (int ntile = 0; ntile < 8; ++ntile) {
        int c = ntile * 8 + 2 * t;
        d0[c]     = O[ntile][0] * i0;
        d0[c + 1] = O[ntile][1] * i0;
        d1[c]     = O[ntile][2] * i1;
        d1[c + 1] = O[ntile][3] * i1;
    }
}

// ---------------------------------------------------------------------------
// LayerNorm(2048) + exact GELU, in-place on g_h.
// ---------------------------------------------------------------------------
__global__ __launch_bounds__(256) void ln_gelu_kernel(
    const float* __restrict__ lng, const float* __restrict__ lnb)
{
    int row = blockIdx.x;
    float* hr = g_h + (size_t)row * 2048;
    int tid = threadIdx.x;
    float v[8];
    float s = 0.f, s2 = 0.f;
#pragma unroll
    for (int i = 0; i < 8; ++i) {
        float t = hr[tid + i * 256];
        v[i] = t; s += t; s2 += t * t;
    }
#pragma unroll
    for (int o = 16; o; o >>= 1) {
        s  += __shfl_xor_sync(0xffffffffu, s,  o);
        s2 += __shfl_xor_sync(0xffffffffu, s2, o);
    }
    __shared__ float rs[8], rs2[8];
    __shared__ float sm, si;
    int wid = tid >> 5, lane = tid & 31;
    if (!lane) { rs[wid] = s; rs2[wid] = s2; }
    __syncthreads();
    if (tid == 0) {
        float S = 0.f, S2 = 0.f;
#pragma unroll
        for (int i = 0; i < 8; ++i) { S += rs[i]; S2 += rs2[i]; }
        float mean = S * (1.f / 2048.f);
        float var = S2 * (1.f / 2048.f) - mean * mean;
        sm = mean;
        si = rsqrtf(var + 1e-5f);
    }
    __syncthreads();
    float mean = sm, inv = si;
#pragma unroll
    for (int i = 0; i < 8; ++i) {
        int col = tid + i * 256;
        float t = (v[i] - mean) * inv * lng[col] + lnb[col];
        t = 0.5f * t * (1.f + erff(t * 0.70710678118654752f));
        hr[col] = t;
    }
}

// ---------------------------------------------------------------------------
extern "C" void kernel_launch(void* const* d_in, const int* in_sizes, int n_in,
                              void* d_out, int out_size)
{
    const float* x       = (const float*)d_in[0];
    const float* enc     = (const float*)d_in[1];
    const float* Wqkv_w  = (const float*)d_in[2];
    const float* Wqkv_b  = (const float*)d_in[3];
    const float* out_w   = (const float*)d_in[4];
    const float* out_b   = (const float*)d_in[5];
    const float* ffn1_w  = (const float*)d_in[6];
    const float* ffn1_b  = (const float*)d_in[7];
    const float* ln_g    = (const float*)d_in[8];
    const float* ln_b    = (const float*)d_in[9];
    const float* ffn2_w  = (const float*)d_in[10];
    const float* ffn2_b  = (const float*)d_in[11];
    float* out = (float*)d_out;

    // 1) QKV projection + scatter to q/k/v   (M=4096, N=3072, K=1024)
    gemm_kernel<<<dim3(3072 / BN, MROWS / BM), 128>>>(
        x, Wqkv_w, Wqkv_b, nullptr, nullptr, MROWS, 3072, 1024, 1);

    // 2) RoPE on q and k
    rope_kernel<<<(2 * BB * HH * NN * HDIM / 2 + 255) / 256, 256>>>(enc);

    // 3) copy x into concat buffer
    copyx_kernel<<<(MROWS * DD / 4) / 256, 256>>>(x);

    // 4) attention -> g_ctx [B,N,H,HD]
    attn_kernel<<<dim3(NN / 128, BB * HH), 256>>>();

    // 5) out projection -> g_xm[:,1024:2048]   (M=4096, N=1024, K=1024)
    gemm_kernel<<<dim3(1024 / BN, MROWS / BM), 128>>>(
        nullptr, out_w, out_b, nullptr, nullptr, MROWS, 1024, 1024, 2);

    // 6) FFN1 -> g_h   (M=4096, N=2048, K=2048)
    gemm_kernel<<<dim3(2048 / BN, MROWS / BM), 128>>>(
        nullptr, ffn1_w, ffn1_b, nullptr, nullptr, MROWS, 2048, 2048, 0);

    // 7) LayerNorm + GELU in-place
    ln_gelu_kernel<<<MROWS, 256>>>(ln_g, ln_b);

    // 8) FFN2 + residual -> d_out   (M=4096, N=1024, K=2048)
    gemm_kernel<<<dim3(1024 / BN, MROWS / BM), 128>>>(
        x, ffn2_w, ffn2_b, out, x, MROWS, 1024, 2048, 3);
}

// round 4
// speedup vs baseline: 3.8461x; 1.1264x over previous
#include <cuda_runtime.h>
#include <math.h>
#include <stdint.h>

// Problem constants
#define BB 4
#define NN 1024
#define DD 1024
#define HH 16
#define HDIM 64
#define MROWS (BB * NN)          // 4096

// Scratch (device globals; no allocations allowed)
__device__ float g_q[BB * HH * NN * HDIM];   // [B,H,N,HD]
__device__ float g_k[BB * HH * NN * HDIM];
__device__ float g_v[BB * HH * NN * HDIM];
__device__ float g_ctx[BB * NN * DD];        // [B,N,H,HD]
__device__ float g_xm[MROWS * 2 * DD];       // concat([x, message]) rows of 2048
__device__ float g_h[MROWS * 2 * DD];        // FFN hidden, rows of 2048

__device__ __forceinline__ void mma_tf32(float* c, const uint32_t* a, const uint32_t* b) {
    asm volatile(
        "mma.sync.aligned.m16n8k8.row.col.f32.tf32.tf32.f32 "
        "{%0,%1,%2,%3}, {%4,%5,%6,%7}, {%8,%9}, {%0,%1,%2,%3};"
        : "+f"(c[0]), "+f"(c[1]), "+f"(c[2]), "+f"(c[3])
        : "r"(a[0]), "r"(a[1]), "r"(a[2]), "r"(a[3]), "r"(b[0]), "r"(b[1]));
}

__device__ __forceinline__ uint32_t smem_u32(const void* p) {
    return (uint32_t)__cvta_generic_to_shared(p);
}
#define CP_ASYNC16(dst, src) \
    asm volatile("cp.async.cg.shared.global [%0], [%1], 16;" :: "r"(dst), "l"(src))
#define CP_COMMIT() asm volatile("cp.async.commit_group;" ::: "memory")
#define CP_WAIT1()  asm volatile("cp.async.wait_group 1;" ::: "memory")

// ---------------------------------------------------------------------------
// TF32 tensor-core GEMM:  C[M,Ncol] = A[M,K] @ W[Ncol,K]^T + bias
// 128x128 block tile, 4 warps of 64x64, 128 threads, 3-stage cp.async.
// fp32 operands fed raw to HMMA (hardware tf32 truncation).
// mode 0: A=g_xm   -> g_h                      (FFN1)
// mode 1: A=Ain(x) -> scatter to g_q/g_k/g_v   (QKV)
// mode 2: A=g_ctx  -> g_xm[:,1024:2048]        (out-proj)
// mode 3: A=g_h    -> Cout = resid + result    (FFN2 + residual)
// ---------------------------------------------------------------------------
#define BM 128
#define BN 128
#define BK 16
#define APITCH 20   // (20*r + k) mod 32 distinct for r in [0,8), k in [0,4)
#define STAGES 3
#define GEMM_SMEM (STAGES * (BM + BN) * APITCH * 4)

__global__ __launch_bounds__(128) void gemm_kernel(
    const float* __restrict__ Ain, const float* __restrict__ W,
    const float* __restrict__ bias, float* __restrict__ Cout,
    const float* __restrict__ resid, int M, int Ncol, int K, int mode)
{
    extern __shared__ float dyn[];
    float (*As)[BM][APITCH] = (float(*)[BM][APITCH])dyn;
    float (*Ws)[BN][APITCH] = (float(*)[BN][APITCH])(dyn + STAGES * BM * APITCH);

    const float* A = (mode == 2) ? g_ctx : (mode == 0) ? g_xm : (mode == 3) ? g_h : Ain;

    int tid = threadIdx.x;
    int lane = tid & 31;
    int wid = tid >> 5;
    int g = lane >> 2, t = lane & 3;
    int wm = wid >> 1;
    int wn = wid & 1;
    int m0 = blockIdx.y * BM, n0 = blockIdx.x * BN;

    float acc[4][8][4];
#pragma unroll
    for (int i = 0; i < 4; ++i)
#pragma unroll
        for (int j = 0; j < 8; ++j)
#pragma unroll
            for (int r = 0; r < 4; ++r) acc[i][j][r] = 0.f;

    int nt = K / BK;
    int lrow = tid >> 2, lkq = (tid & 3) * 4;   // this thread's load slot

    auto issue = [&](int s, int k0) {
#pragma unroll
        for (int h = 0; h < 4; ++h) {
            int row = lrow + h * 32;
            CP_ASYNC16(smem_u32(&As[s][row][lkq]),
                       A + (size_t)(m0 + row) * K + k0 + lkq);
            CP_ASYNC16(smem_u32(&Ws[s][row][lkq]),
                       W + (size_t)(n0 + row) * K + k0 + lkq);
        }
        CP_COMMIT();
    };

    issue(0, 0);
    issue(1, BK);

    for (int tt = 0; tt < nt; ++tt) {
        int buf = tt % STAGES;
        CP_WAIT1();
        __syncthreads();

#pragma unroll
        for (int kk = 0; kk < BK; kk += 8) {
            int ko = kk + t;
            uint32_t af[4][4], bf[8][2];
#pragma unroll
            for (int tm = 0; tm < 4; ++tm) {
                int r = wm * 64 + tm * 16 + g;
                af[tm][0] = __float_as_uint(As[buf][r][ko]);
                af[tm][1] = __float_as_uint(As[buf][r + 8][ko]);
                af[tm][2] = __float_as_uint(As[buf][r][ko + 4]);
                af[tm][3] = __float_as_uint(As[buf][r + 8][ko + 4]);
            }
#pragma unroll
            for (int tn = 0; tn < 8; ++tn) {
                int c = wn * 64 + tn * 8 + g;
                bf[tn][0] = __float_as_uint(Ws[buf][c][ko]);
                bf[tn][1] = __float_as_uint(Ws[buf][c][ko + 4]);
            }
#pragma unroll
            for (int tm = 0; tm < 4; ++tm)
#pragma unroll
                for (int tn = 0; tn < 8; ++tn)
                    mma_tf32(acc[tm][tn], af[tm], bf[tn]);
        }

        int nk = tt + 2;
        if (nk < nt) issue(nk % STAGES, nk * BK);
        else CP_COMMIT();   // empty group keeps wait_group arithmetic exact
        __syncthreads();
    }

    // epilogue: c0:(r, 2t) c1:(r, 2t+1) c2:(r+8, 2t) c3:(r+8, 2t+1)
    int rbase = m0 + wm * 64 + g;
    int cbase = n0 + wn * 64 + 2 * t;
#pragma unroll
    for (int tm = 0; tm < 4; ++tm) {
#pragma unroll
        for (int tn = 0; tn < 8; ++tn) {
#pragma unroll
            for (int r = 0; r < 4; ++r) {
                int m = rbase + tm * 16 + ((r >> 1) ? 8 : 0);
                int col = cbase + tn * 8 + (r & 1);
                float v = acc[tm][tn][r] + bias[col];
                int b = m >> 10, n = m & 1023;
                if (mode == 0) {
                    g_h[(size_t)m * Ncol + col] = v;
                } else if (mode == 2) {
                    g_xm[(size_t)m * 2048 + 1024 + col] = v;
                } else if (mode == 3) {
                    Cout[(size_t)m * Ncol + col] = v + resid[(size_t)m * Ncol + col];
                } else { // mode 1: QKV scatter
                    int h = col / 192;
                    int rem = col - h * 192;
                    int d = rem / 3;
                    int s = rem - d * 3;
                    size_t di = (((size_t)(b * HH + h)) * NN + n) * HDIM + d;
                    if (s == 0) g_q[di] = v;
                    else if (s == 1) g_k[di] = v;
                    else g_v[di] = v;
                }
            }
        }
    }
}

// ---------------------------------------------------------------------------
// RoPE in-place on g_q and g_k.  encoding: [2, B, 1, N, HD]
// ---------------------------------------------------------------------------
__global__ void rope_kernel(const float* __restrict__ enc)
{
    const int PH = BB * HH * NN * HDIM / 2;
    int p = blockIdx.x * blockDim.x + threadIdx.x;
    if (p >= 2 * PH) return;
    float* t = (p < PH) ? g_q : g_k;
    int pp = (p < PH) ? p : p - PH;
    int e = pp * 2;
    int d = e & 63;
    int n = (e >> 6) & 1023;
    int bh = e >> 16;
    int b = bh >> 4;
    float t0 = t[e], t1 = t[e + 1];
    size_t eb = ((size_t)(b * NN + n)) * HDIM + d;
    const int SINOFF = BB * NN * HDIM;
    float c0 = enc[eb], c1 = enc[eb + 1];
    float s0 = enc[eb + SINOFF], s1 = enc[eb + SINOFF + 1];
    t[e]     = t0 * c0 - t1 * s0;
    t[e + 1] = t1 * c1 + t0 * s1;
}

// copy x into first half of concat buffer
__global__ void copyx_kernel(const float* __restrict__ x)
{
    int i = blockIdx.x * 256 + threadIdx.x;
    float4 v = ((const float4*)x)[i];
    int m = i >> 8;
    int c = i & 255;
    ((float4*)g_xm)[(size_t)m * 512 + c] = v;
}

// ---------------------------------------------------------------------------
// Flash attention on tensor cores (tf32 m16n8k8, raw fp32 operands).
// Block: 128 query rows (8 warps x 16), key tiles of 64, online softmax.
// ---------------------------------------------------------------------------
#define KP 68
#define VP 65

__global__ __launch_bounds__(256) void attn_kernel()
{
    __shared__ float Ks[64][KP];
    __shared__ float VsT[64][VP];

    int bh = blockIdx.y;
    int qt = blockIdx.x;
    int tid = threadIdx.x;
    int lane = tid & 31;
    int wid = tid >> 5;
    int g = lane >> 2, t = lane & 3;

    const float* qbase = g_q + (size_t)bh * NN * HDIM + (size_t)qt * 128 * HDIM;
    const float* kbase = g_k + (size_t)bh * NN * HDIM;
    const float* vbase = g_v + (size_t)bh * NN * HDIM;

    // Q fragments (pre-scaled): warp rows wid*16+g, wid*16+g+8; 8 hd-chunks
    uint32_t qf[8][4];
    {
        const float* q0 = qbase + (size_t)(wid * 16 + g) * HDIM;
        const float* q1 = q0 + 8 * HDIM;
#pragma unroll
        for (int kc = 0; kc < 8; ++kc) {
            int k0 = kc * 8 + t;
            qf[kc][0] = __float_as_uint(q0[k0] * 0.125f);
            qf[kc][1] = __float_as_uint(q1[k0] * 0.125f);
            qf[kc][2] = __float_as_uint(q0[k0 + 4] * 0.125f);
            qf[kc][3] = __float_as_uint(q1[k0 + 4] * 0.125f);
        }
    }

    float m0 = -1e30f, m1 = -1e30f, l0 = 0.f, l1 = 0.f;
    float O[8][4];
#pragma unroll
    for (int i = 0; i < 8; ++i)
#pragma unroll
        for (int r = 0; r < 4; ++r) O[i][r] = 0.f;

    const int sl0 = (lane & ~3) | (t >> 1);
    const int sl1 = sl0 + 2;

    for (int kt = 0; kt < 16; ++kt) {
        const float* kb = kbase + (size_t)kt * 64 * HDIM;
        const float* vb = vbase + (size_t)kt * 64 * HDIM;
#pragma unroll
        for (int h2 = 0; h2 < 4; ++h2) {
            int f = tid + h2 * 256;
            int r = f >> 4, cq = (f & 15) * 4;
            float4 kv = *(const float4*)(kb + (size_t)r * HDIM + cq);
            *(float4*)&Ks[r][cq] = kv;
            float4 vv = *(const float4*)(vb + (size_t)r * HDIM + cq);
            VsT[cq + 0][r] = vv.x;
            VsT[cq + 1][r] = vv.y;
            VsT[cq + 2][r] = vv.z;
            VsT[cq + 3][r] = vv.w;
        }
        __syncthreads();

        // S = Q K^T  (16 rows x 64 key cols per warp)
        float S[8][4];
#pragma unroll
        for (int i = 0; i < 8; ++i)
#pragma unroll
            for (int r = 0; r < 4; ++r) S[i][r] = 0.f;
#pragma unroll
        for (int kc = 0; kc < 8; ++kc) {
#pragma unroll
            for (int ntile = 0; ntile < 8; ++ntile) {
                uint32_t bf[2];
                bf[0] = __float_as_uint(Ks[ntile * 8 + g][kc * 8 + t]);
                bf[1] = __float_as_uint(Ks[ntile * 8 + g][kc * 8 + t + 4]);
                mma_tf32(S[ntile], qf[kc], bf);
            }
        }

        // online softmax
        float tm0 = -1e30f, tm1 = -1e30f;
#pragma unroll
        for (int i = 0; i < 8; ++i) {
            tm0 = fmaxf(tm0, fmaxf(S[i][0], S[i][1]));
            tm1 = fmaxf(tm1, fmaxf(S[i][2], S[i][3]));
        }
        tm0 = fmaxf(tm0, __shfl_xor_sync(0xffffffffu, tm0, 1));
        tm0 = fmaxf(tm0, __shfl_xor_sync(0xffffffffu, tm0, 2));
        tm1 = fmaxf(tm1, __shfl_xor_sync(0xffffffffu, tm1, 1));
        tm1 = fmaxf(tm1, __shfl_xor_sync(0xffffffffu, tm1, 2));
        float mn0 = fmaxf(m0, tm0), mn1 = fmaxf(m1, tm1);
        float a0 = __expf(m0 - mn0), a1 = __expf(m1 - mn1);
        m0 = mn0; m1 = mn1;

        float ps0 = 0.f, ps1 = 0.f;
#pragma unroll
        for (int i = 0; i < 8; ++i) {
            float p0 = __expf(S[i][0] - mn0);
            float p1 = __expf(S[i][1] - mn0);
            float p2 = __expf(S[i][2] - mn1);
            float p3 = __expf(S[i][3] - mn1);
            ps0 += p0 + p1; ps1 += p2 + p3;
            S[i][0] = p0; S[i][1] = p1; S[i][2] = p2; S[i][3] = p3;
        }
        ps0 += __shfl_xor_sync(0xffffffffu, ps0, 1);
        ps0 += __shfl_xor_sync(0xffffffffu, ps0, 2);
        ps1 += __shfl_xor_sync(0xffffffffu, ps1, 1);
        ps1 += __shfl_xor_sync(0xffffffffu, ps1, 2);
        l0 = l0 * a0 + ps0;
        l1 = l1 * a1 + ps1;
#pragma unroll
        for (int i = 0; i < 8; ++i) {
            O[i][0] *= a0; O[i][1] *= a0; O[i][2] *= a1; O[i][3] *= a1;
        }

        // O += P @ V : per key chunk kc build A-frag of P via quad shuffles
#pragma unroll
        for (int kc = 0; kc < 8; ++kc) {
            float v00 = __shfl_sync(0xffffffffu, S[kc][0], sl0);
            float v01 = __shfl_sync(0xffffffffu, S[kc][1], sl0);
            float v10 = __shfl_sync(0xffffffffu, S[kc][2], sl0);
            float v11 = __shfl_sync(0xffffffffu, S[kc][3], sl0);
            float v20 = __shfl_sync(0xffffffffu, S[kc][0], sl1);
            float v21 = __shfl_sync(0xffffffffu, S[kc][1], sl1);
            float v30 = __shfl_sync(0xffffffffu, S[kc][2], sl1);
            float v31 = __shfl_sync(0xffffffffu, S[kc][3], sl1);
            uint32_t af[4];
            af[0] = __float_as_uint((t & 1) ? v01 : v00);
            af[1] = __float_as_uint((t & 1) ? v11 : v10);
            af[2] = __float_as_uint((t & 1) ? v21 : v20);
            af[3] = __float_as_uint((t & 1) ? v31 : v30);
#pragma unroll
            for (int ntile = 0; ntile < 8; ++ntile) {
                uint32_t bf[2];
                bf[0] = __float_as_uint(VsT[ntile * 8 + g][kc * 8 + t]);
                bf[1] = __float_as_uint(VsT[ntile * 8 + g][kc * 8 + t + 4]);
                mma_tf32(O[ntile], af, bf);
            }
        }
        __syncthreads();
    }

    float i0 = 1.f / l0, i1 = 1.f / l1;
    int b = bh >> 4, h = bh & 15;
    int r0 = qt * 128 + wid * 16 + g;
    float* d0 = g_ctx + (((size_t)(b * NN + r0)) * HH + h) * HDIM;
    float* d1 = g_ctx + (((size_t)(b * NN + r0 + 8)) * HH + h) * HDIM;
#pragma unroll
    for (int ntile = 0; ntile < 8; ++ntile) {
        int c = ntile * 8 + 2 * t;
        d0[c]     = O[ntile][0] * i0;
        d0[c + 1] = O[ntile][1] * i0;
        d1[c]     = O[ntile][2] * i1;
        d1[c + 1] = O[ntile][3] * i1;
    }
}

// ---------------------------------------------------------------------------
// LayerNorm(2048) + exact GELU, in-place on g_h.
// ---------------------------------------------------------------------------
__global__ __launch_bounds__(256) void ln_gelu_kernel(
    const float* __restrict__ lng, const float* __restrict__ lnb)
{
    int row = blockIdx.x;
    float* hr = g_h + (size_t)row * 2048;
    int tid = threadIdx.x;
    float v[8];
    float s = 0.f, s2 = 0.f;
#pragma unroll
    for (int i = 0; i < 8; ++i) {
        float t = hr[tid + i * 256];
        v[i] = t; s += t; s2 += t * t;
    }
#pragma unroll
    for (int o = 16; o; o >>= 1) {
        s  += __shfl_xor_sync(0xffffffffu, s,  o);
        s2 += __shfl_xor_sync(0xffffffffu, s2, o);
    }
    __shared__ float rs[8], rs2[8];
    __shared__ float sm, si;
    int wid = tid >> 5, lane = tid & 31;
    if (!lane) { rs[wid] = s; rs2[wid] = s2; }
    __syncthreads();
    if (tid == 0) {
        float S = 0.f, S2 = 0.f;
#pragma unroll
        for (int i = 0; i < 8; ++i) { S += rs[i]; S2 += rs2[i]; }
        float mean = S * (1.f / 2048.f);
        float var = S2 * (1.f / 2048.f) - mean * mean;
        sm = mean;
        si = rsqrtf(var + 1e-5f);
    }
    __syncthreads();
    float mean = sm, inv = si;
#pragma unroll
    for (int i = 0; i < 8; ++i) {
        int col = tid + i * 256;
        float t = (v[i] - mean) * inv * lng[col] + lnb[col];
        t = 0.5f * t * (1.f + erff(t * 0.70710678118654752f));
        hr[col] = t;
    }
}

// ---------------------------------------------------------------------------
extern "C" void kernel_launch(void* const* d_in, const int* in_sizes, int n_in,
                              void* d_out, int out_size)
{
    const float* x       = (const float*)d_in[0];
    const float* enc     = (const float*)d_in[1];
    const float* Wqkv_w  = (const float*)d_in[2];
    const float* Wqkv_b  = (const float*)d_in[3];
    const float* out_w   = (const float*)d_in[4];
    const float* out_b   = (const float*)d_in[5];
    const float* ffn1_w  = (const float*)d_in[6];
    const float* ffn1_b  = (const float*)d_in[7];
    const float* ln_g    = (const float*)d_in[8];
    const float* ln_b    = (const float*)d_in[9];
    const float* ffn2_w  = (const float*)d_in[10];
    const float* ffn2_b  = (const float*)d_in[11];
    float* out = (float*)d_out;

    cudaFuncSetAttribute(gemm_kernel,
                         cudaFuncAttributeMaxDynamicSharedMemorySize, GEMM_SMEM);

    // 1) QKV projection + scatter to q/k/v   (M=4096, N=3072, K=1024)
    gemm_kernel<<<dim3(3072 / BN, MROWS / BM), 128, GEMM_SMEM>>>(
        x, Wqkv_w, Wqkv_b, nullptr, nullptr, MROWS, 3072, 1024, 1);

    // 2) RoPE on q and k
    rope_kernel<<<(2 * BB * HH * NN * HDIM / 2 + 255) / 256, 256>>>(enc);

    // 3) copy x into concat buffer
    copyx_kernel<<<(MROWS * DD / 4) / 256, 256>>>(x);

    // 4) attention -> g_ctx [B,N,H,HD]
    attn_kernel<<<dim3(NN / 128, BB * HH), 256>>>();

    // 5) out projection -> g_xm[:,1024:2048]   (M=4096, N=1024, K=1024)
    gemm_kernel<<<dim3(1024 / BN, MROWS / BM), 128, GEMM_SMEM>>>(
        nullptr, out_w, out_b, nullptr, nullptr, MROWS, 1024, 1024, 2);

    // 6) FFN1 -> g_h   (M=4096, N=2048, K=2048)
    gemm_kernel<<<dim3(2048 / BN, MROWS / BM), 128, GEMM_SMEM>>>(
        nullptr, ffn1_w, ffn1_b, nullptr, nullptr, MROWS, 2048, 2048, 0);

    // 7) LayerNorm + GELU in-place
    ln_gelu_kernel<<<MROWS, 256>>>(ln_g, ln_b);

    // 8) FFN2 + residual -> d_out   (M=4096, N=1024, K=2048)
    gemm_kernel<<<dim3(1024 / BN, MROWS / BM), 128, GEMM_SMEM>>>(
        x, ffn2_w, ffn2_b, out, x, MROWS, 1024, 2048, 3);
}